// round 7
// baseline (speedup 1.0000x reference)
#include <cuda_runtime.h>
#include <cuda_bf16.h>
#include <math.h>
#include <stdint.h>

// Problem constants
#define Bx  2
#define Lx  2048
#define Dx  1024
#define Hx  16
#define DKx 64
#define BHx (Bx*Hx)

// ---------------- device scratch (no allocations allowed) ----------------
__device__ float g_Q[(size_t)BHx*Lx*DKx];      // [B,H,L,DK]
__device__ float g_K[(size_t)BHx*Lx*DKx];
__device__ float g_V[(size_t)BHx*Lx*DKx];
__device__ float g_attn[(size_t)Bx*Lx*Dx];     // [B,L,H*DK]
__device__ float g_bias[(size_t)Bx*Lx*Lx];     // -|lam|*log1p(|ti-tj|/denom)
__device__ float g_scal[2];                    // [0]=1/denom, [1]=-|lam|
// packed bf16 hi/lo operands (u32 = bf16x2 pair along k)
__device__ uint32_t g_xh[(size_t)4096*512], g_xl[(size_t)4096*512];   // x, later attn-out
__device__ uint32_t g_wh[(size_t)4*1024*512], g_wl[(size_t)4*1024*512];

// ---------------- helpers ----------------
__device__ __forceinline__ uint32_t to_tf32(float x) {
    uint32_t r;
    asm("cvt.rna.tf32.f32 %0, %1;" : "=r"(r) : "f"(x));
    return r;
}
__device__ __forceinline__ float tf32f(float x) { return __uint_as_float(to_tf32(x)); }

// split two floats into packed bf16x2 hi and lo
__device__ __forceinline__ void split2(float2 v, uint32_t& hi, uint32_t& lo) {
    __nv_bfloat162 h = __floats2bfloat162_rn(v.x, v.y);
    float hx = __bfloat162float(h.x);
    float hy = __bfloat162float(h.y);
    __nv_bfloat162 l = __floats2bfloat162_rn(v.x - hx, v.y - hy);
    hi = *(uint32_t*)&h;
    lo = *(uint32_t*)&l;
}

__device__ __forceinline__ void mma16n8k8(float* c, const uint32_t* a, const uint32_t* b) {
    asm volatile(
        "mma.sync.aligned.m16n8k8.row.col.f32.tf32.tf32.f32 "
        "{%0,%1,%2,%3}, {%4,%5,%6,%7}, {%8,%9}, {%0,%1,%2,%3};"
        : "+f"(c[0]), "+f"(c[1]), "+f"(c[2]), "+f"(c[3])
        : "r"(a[0]), "r"(a[1]), "r"(a[2]), "r"(a[3]), "r"(b[0]), "r"(b[1]));
}
__device__ __forceinline__ void mma_bf16(float* c, const uint32_t* a, uint32_t b0, uint32_t b1) {
    asm volatile(
        "mma.sync.aligned.m16n8k16.row.col.f32.bf16.bf16.f32 "
        "{%0,%1,%2,%3}, {%4,%5,%6,%7}, {%8,%9}, {%0,%1,%2,%3};"
        : "+f"(c[0]), "+f"(c[1]), "+f"(c[2]), "+f"(c[3])
        : "r"(a[0]), "r"(a[1]), "r"(a[2]), "r"(a[3]), "r"(b0), "r"(b1));
}

__device__ __forceinline__ void cpasync16(uint32_t s, const void* g) {
    asm volatile("cp.async.cg.shared.global [%0], [%1], 16;" :: "r"(s), "l"(g));
}
__device__ __forceinline__ uint32_t smem_u32p(const void* p) {
    uint32_t a;
    asm("{ .reg .u64 t; cvta.to.shared.u64 t, %1; cvt.u32.u64 %0, t; }" : "=r"(a) : "l"(p));
    return a;
}

// Fast exp on the FMA pipe
__device__ __forceinline__ float fexp(float x) {
    x = fmaxf(x, -80.0f);
    float z = fmaf(x, 1.4426950408889634f, 12582912.0f);
    int   ni = __float_as_int(z) - 0x4B400000;
    float fn = z - 12582912.0f;
    float f  = fmaf(x, 1.4426950408889634f, -fn);
    float p = 0.0013333558f;
    p = fmaf(p, f, 0.0096181291f);
    p = fmaf(p, f, 0.0555041087f);
    p = fmaf(p, f, 0.2402265069f);
    p = fmaf(p, f, 0.6931471806f);
    p = fmaf(p, f, 1.0f);
    return __int_as_float(__float_as_int(p) + (ni << 23));
}

// ---------------- denom + lam scalars ----------------
__global__ void k_denom(const float* __restrict__ ts, const float* __restrict__ lam)
{
    float m = 1.0f;
    for (int b = 0; b < Bx; b++) {
        float d = ts[b*Lx + (Lx-1)] - ts[b*Lx + 0];
        m = fmaxf(m, d);
    }
    g_scal[0] = 1.0f / m;
    g_scal[1] = -fabsf(lam[0]);
}

// ---------------- temporal bias precompute ----------------
__global__ __launch_bounds__(256) void k_bias(const float* __restrict__ ts)
{
    long idx = (long)blockIdx.x * 256 + threadIdx.x;
    int  j = (int)(idx & (Lx-1));
    long t = idx >> 11;
    int  i = (int)(t & (Lx-1));
    int  b = (int)(t >> 11);
    float d = fabsf(ts[b*Lx + i] - ts[b*Lx + j]);
    g_bias[idx] = g_scal[1] * log1pf(d * g_scal[0]);
}

// ---------------- pack fp32 -> bf16 hi/lo pairs ----------------
__global__ __launch_bounds__(256) void k_pack(const float* __restrict__ s,
                                              uint32_t* __restrict__ h,
                                              uint32_t* __restrict__ l)
{
    int i = blockIdx.x * 256 + threadIdx.x;
    float2 v = *(const float2*)(s + 2 * (size_t)i);
    split2(v, h[i], l[i]);
}
// pack the 4 weight matrices (z selects)
__global__ __launch_bounds__(256) void k_packw(const float* __restrict__ w0,
                                               const float* __restrict__ w1,
                                               const float* __restrict__ w2,
                                               const float* __restrict__ w3)
{
    const float* s = (blockIdx.z == 0) ? w0 : (blockIdx.z == 1) ? w1 :
                     (blockIdx.z == 2) ? w2 : w3;
    size_t off = (size_t)blockIdx.z * 1024 * 512;
    int i = blockIdx.x * 256 + threadIdx.x;
    float2 v = *(const float2*)(s + 2 * (size_t)i);
    split2(v, g_wh[off + i], g_wl[off + i]);
}

// ---------------- bf16 hi/lo 3-term GEMM, cp.async pipelined ----------------
// out[m,n] = sum_k A[m,k]*W[n,k] + bias[n];  A,W pre-packed bf16 hi/lo pairs.
// BM=BN=128, BK=32 (16 pairs). 256 threads = 8 warps (2m x 4n), warp tile 64x32.
#define GLD 20                         // padded row stride in u32 (16 data + 4 pad)
#define GST (128 * GLD)                // u32 per matrix tile per stage
#define GSTAGE (4 * GST)               // Ah|Al|Bh|Bl
#define GEMM2_SMEM (2 * GSTAGE * 4)    // 81920 B

template<bool SCATTER>
__global__ __launch_bounds__(256, 2) void k_gemm_bf16(
    const float* __restrict__ b0, const float* __restrict__ b1,
    const float* __restrict__ b2, float* __restrict__ outp)
{
    extern __shared__ uint32_t smu[];
    const uint32_t sb = smem_u32p(smu);

    const float* bias;
    float* out;
    int widx;
    if (SCATTER) {
        widx = blockIdx.z;
        if (widx == 0)      { bias = b0; out = g_Q; }
        else if (widx == 1) { bias = b1; out = g_K; }
        else                { bias = b2; out = g_V; }
    } else {
        widx = 3; bias = b0; out = outp;
    }
    const uint32_t* Ah = g_xh;
    const uint32_t* Al = g_xl;
    const uint32_t* Bh = g_wh + (size_t)widx * 1024 * 512;
    const uint32_t* Bl = g_wl + (size_t)widx * 1024 * 512;

    const int tid = threadIdx.x;
    const int wid = tid >> 5, lane = tid & 31;
    const int wm = wid >> 2, wn = wid & 3;
    const int lr = lane >> 2, lc = lane & 3;
    const int m0 = blockIdx.y * 128;
    const int n0 = blockIdx.x * 128;

    float c[4][4][4];
#pragma unroll
    for (int i = 0; i < 4; i++)
#pragma unroll
        for (int j = 0; j < 4; j++)
#pragma unroll
            for (int q = 0; q < 4; q++) c[i][j][q] = 0.f;

    auto load_stage = [&](int st, int kp0) {
        const uint32_t base = sb + st * GSTAGE * 4;
        const int row = tid >> 2, ch = tid & 3;         // 64 rows per 256-thread pass? no:
        // 128 rows x 4 chunks = 512 chunks per matrix; 2 passes of 256
#pragma unroll
        for (int t = 0; t < 2; t++) {
            int i = tid + t * 256;
            int r = i >> 2, cc = i & 3;
            size_t ga = (size_t)(m0 + r) * 512 + kp0 + cc * 4;
            uint32_t ds = (r * GLD + cc * 4) * 4;
            cpasync16(base + ds,             Ah + ga);
            cpasync16(base + GST * 4 + ds,   Al + ga);
            size_t gb = (size_t)(n0 + r) * 512 + kp0 + cc * 4;
            cpasync16(base + 2 * GST * 4 + ds, Bh + gb);
            cpasync16(base + 3 * GST * 4 + ds, Bl + gb);
        }
        asm volatile("cp.async.commit_group;");
        (void)row; (void)ch;
    };

    load_stage(0, 0);

    const int NITER = 32;                 // 1024 / 32
    for (int it = 0; it < NITER; ++it) {
        const int buf = it & 1;
        if (it + 1 < NITER) {
            load_stage(1 - buf, (it + 1) * 16);
            asm volatile("cp.async.wait_group 1;");
        } else {
            asm volatile("cp.async.wait_group 0;");
        }
        __syncthreads();

        const uint32_t* AhS = smu + buf * GSTAGE;
        const uint32_t* AlS = AhS + GST;
        const uint32_t* BhS = AhS + 2 * GST;
        const uint32_t* BlS = AhS + 3 * GST;
#pragma unroll
        for (int ks = 0; ks < 2; ks++) {
            uint32_t aH[4][4], aL[4][4];
#pragma unroll
            for (int mt = 0; mt < 4; mt++) {
                const uint32_t* p = AhS + (wm * 64 + mt * 16 + lr) * GLD + ks * 8 + lc;
                aH[mt][0] = p[0]; aH[mt][2] = p[4];
                aH[mt][1] = p[8 * GLD]; aH[mt][3] = p[8 * GLD + 4];
                const uint32_t* q = AlS + (wm * 64 + mt * 16 + lr) * GLD + ks * 8 + lc;
                aL[mt][0] = q[0]; aL[mt][2] = q[4];
                aL[mt][1] = q[8 * GLD]; aL[mt][3] = q[8 * GLD + 4];
            }
#pragma unroll
            for (int nt = 0; nt < 4; nt++) {
                const uint32_t* pb = BhS + (wn * 32 + nt * 8 + lr) * GLD + ks * 8 + lc;
                uint32_t bH0 = pb[0], bH1 = pb[4];
                const uint32_t* qb = BlS + (wn * 32 + nt * 8 + lr) * GLD + ks * 8 + lc;
                uint32_t bL0 = qb[0], bL1 = qb[4];
#pragma unroll
                for (int mt = 0; mt < 4; mt++) {
                    mma_bf16(c[mt][nt], aH[mt], bH0, bH1);
                    mma_bf16(c[mt][nt], aH[mt], bL0, bL1);
                    mma_bf16(c[mt][nt], aL[mt], bH0, bH1);
                }
            }
        }
        __syncthreads();
    }

    // epilogue: add bias, store
#pragma unroll
    for (int mt = 0; mt < 4; mt++) {
        const int mA = m0 + wm * 64 + mt * 16 + lr;
        const int mB = mA + 8;
#pragma unroll
        for (int nt = 0; nt < 4; nt++) {
            const int n = n0 + wn * 32 + nt * 8 + 2 * lc;
            const float bn0 = bias[n], bn1 = bias[n + 1];
            float2 v0 = make_float2(c[mt][nt][0] + bn0, c[mt][nt][1] + bn1);
            float2 v1 = make_float2(c[mt][nt][2] + bn0, c[mt][nt][3] + bn1);
            if (SCATTER) {
                const int h = n >> 6, dk = n & 63;
                const int bA = mA >> 11, lA = mA & (Lx - 1);
                const int bB = mB >> 11, lB = mB & (Lx - 1);
                *(float2*)(out + (((size_t)bA*Hx + h)*Lx + lA)*DKx + dk) = v0;
                *(float2*)(out + (((size_t)bB*Hx + h)*Lx + lB)*DKx + dk) = v1;
            } else {
                *(float2*)(out + (size_t)mA * Dx + n) = v0;
                *(float2*)(out + (size_t)mB * Dx + n) = v1;
            }
        }
    }
}

// ---------------- mma.sync flash attention (unchanged from R5) ----------------
#define AO_KH 0
#define AO_KL 2304
#define AO_V  4608
#define AO_P  9216
#define ATTN_SMEM ((9216 + 4352) * 4)

__global__ __launch_bounds__(128, 3) void k_attn_mma()
{
    extern __shared__ uint32_t smu[];
    uint32_t* KhU = smu + AO_KH;
    uint32_t* KlU = smu + AO_KL;
    float*    Vs  = (float*)(smu + AO_V);
    float*    Ps  = (float*)(smu + AO_P);
    const uint32_t* VsU = (const uint32_t*)Vs;
    const uint32_t* PsU = (const uint32_t*)Ps;

    const int tid = threadIdx.x;
    const int wid = tid >> 5, lane = tid & 31;
    const int lr = lane >> 2, lc = lane & 3;
    const int qt = gridDim.x - 1 - blockIdx.x;
    const int bh = blockIdx.y;
    const int b = bh >> 4, h = bh & 15;
    const int qi0 = qt * 64;
    const int r0 = wid * 16;
    const int qrA = qi0 + r0 + lr;
    const int qrB = qrA + 8;

    const float* Qg = g_Q + (size_t)bh*Lx*DKx;
    const float* Kg = g_K + (size_t)bh*Lx*DKx;
    const float* Vg = g_V + (size_t)bh*Lx*DKx;
    const float* biasB = g_bias + (size_t)b*Lx*Lx;

    uint32_t qH[4][4], qL[4][4];
#pragma unroll
    for (int ks = 0; ks < 4; ks++) {
        const int kb = 16 * ks + 2 * lc;
        float2 v;
        v = *(const float2*)(Qg + (size_t)qrA * DKx + kb);
        split2(v, qH[ks][0], qL[ks][0]);
        v = *(const float2*)(Qg + (size_t)qrB * DKx + kb);
        split2(v, qH[ks][1], qL[ks][1]);
        v = *(const float2*)(Qg + (size_t)qrA * DKx + kb + 8);
        split2(v, qH[ks][2], qL[ks][2]);
        v = *(const float2*)(Qg + (size_t)qrB * DKx + kb + 8);
        split2(v, qH[ks][3], qL[ks][3]);
    }

    float cO[8][4];
#pragma unroll
    for (int nt = 0; nt < 8; nt++)
#pragma unroll
        for (int q = 0; q < 4; q++) cO[nt][q] = 0.f;
    float mA = -1e30f, mB = -1e30f, lA = 0.f, lB = 0.f;

    const int nkt = qt + 1;

    for (int kt = 0; kt < nkt; kt++) {
        const int kj0 = kt * 64;
        __syncthreads();
#pragma unroll
        for (int t = 0; t < 8; t++) {
            int i = tid + t * 128;
            int row = i >> 4, c4 = i & 15;
            float4 kv = *(const float4*)(Kg + (size_t)(kj0 + row) * DKx + c4 * 4);
            uint32_t h0, l0, h1, l1;
            split2(make_float2(kv.x, kv.y), h0, l0);
            split2(make_float2(kv.z, kv.w), h1, l1);
            KhU[row * 36 + c4 * 2]     = h0;
            KhU[row * 36 + c4 * 2 + 1] = h1;
            KlU[row * 36 + c4 * 2]     = l0;
            KlU[row * 36 + c4 * 2 + 1] = l1;
            float4 vv = *(const float4*)(Vg + (size_t)(kj0 + row) * DKx + c4 * 4);
            float* pv = Vs + row * 72 + c4 * 4;
            pv[0] = tf32f(vv.x); pv[1] = tf32f(vv.y);
            pv[2] = tf32f(vv.z); pv[3] = tf32f(vv.w);
        }
        __syncthreads();

        float cS[8][4];
#pragma unroll
        for (int nt = 0; nt < 8; nt++)
#pragma unroll
            for (int q = 0; q < 4; q++) cS[nt][q] = 0.f;

#pragma unroll
        for (int ks = 0; ks < 4; ks++) {
#pragma unroll
            for (int nt = 0; nt < 8; nt++) {
                const uint32_t* ph = KhU + (nt * 8 + lr) * 36 + ks * 8 + lc;
                const uint32_t* pl = KlU + (nt * 8 + lr) * 36 + ks * 8 + lc;
                uint32_t bH0 = ph[0], bH1 = ph[4];
                uint32_t bL0 = pl[0], bL1 = pl[4];
                mma_bf16(cS[nt], qH[ks], bH0, bH1);
                mma_bf16(cS[nt], qH[ks], bL0, bL1);
                mma_bf16(cS[nt], qL[ks], bH0, bH1);
            }
        }

        const bool domask = (kt == qt);
        float rmA = -1e30f, rmB = -1e30f;
#pragma unroll
        for (int nt = 0; nt < 8; nt++) {
            const int kc = kj0 + nt * 8 + 2 * lc;
            float2 biA = *(const float2*)(biasB + (size_t)qrA * Lx + kc);
            float2 biB = *(const float2*)(biasB + (size_t)qrB * Lx + kc);
            float v0 = fmaf(cS[nt][0], 0.125f, biA.x);
            float v1 = fmaf(cS[nt][1], 0.125f, biA.y);
            float v2 = fmaf(cS[nt][2], 0.125f, biB.x);
            float v3 = fmaf(cS[nt][3], 0.125f, biB.y);
            if (domask) {
                if (kc     > qrA) v0 = -1e30f;
                if (kc + 1 > qrA) v1 = -1e30f;
                if (kc     > qrB) v2 = -1e30f;
                if (kc + 1 > qrB) v3 = -1e30f;
            }
            cS[nt][0] = v0; cS[nt][1] = v1; cS[nt][2] = v2; cS[nt][3] = v3;
            rmA = fmaxf(rmA, fmaxf(v0, v1));
            rmB = fmaxf(rmB, fmaxf(v2, v3));
        }
        rmA = fmaxf(rmA, __shfl_xor_sync(0xffffffffu, rmA, 1));
        rmA = fmaxf(rmA, __shfl_xor_sync(0xffffffffu, rmA, 2));
        rmB = fmaxf(rmB, __shfl_xor_sync(0xffffffffu, rmB, 1));
        rmB = fmaxf(rmB, __shfl_xor_sync(0xffffffffu, rmB, 2));

        const float mnA = fmaxf(mA, rmA);
        const float mnB = fmaxf(mB, rmB);
        const float scA = fexp(mA - mnA);
        const float scB = fexp(mB - mnB);
        mA = mnA; mB = mnB;

        float rsA = 0.f, rsB = 0.f;
#pragma unroll
        for (int nt = 0; nt < 8; nt++) {
            float p0 = fexp(cS[nt][0] - mnA);
            float p1 = fexp(cS[nt][1] - mnA);
            float p2 = fexp(cS[nt][2] - mnB);
            float p3 = fexp(cS[nt][3] - mnB);
            rsA += p0 + p1;
            rsB += p2 + p3;
            cS[nt][0] = p0; cS[nt][1] = p1; cS[nt][2] = p2; cS[nt][3] = p3;
        }
        rsA += __shfl_xor_sync(0xffffffffu, rsA, 1);
        rsA += __shfl_xor_sync(0xffffffffu, rsA, 2);
        rsB += __shfl_xor_sync(0xffffffffu, rsB, 1);
        rsB += __shfl_xor_sync(0xffffffffu, rsB, 2);
        lA = lA * scA + rsA;
        lB = lB * scB + rsB;
#pragma unroll
        for (int nt = 0; nt < 8; nt++) {
            cO[nt][0] *= scA; cO[nt][1] *= scA;
            cO[nt][2] *= scB; cO[nt][3] *= scB;
        }

#pragma unroll
        for (int nt = 0; nt < 8; nt++) {
            float* pA = Ps + (r0 + lr) * 68 + nt * 8 + 2 * lc;
            float* pB = Ps + (r0 + lr + 8) * 68 + nt * 8 + 2 * lc;
            pA[0] = tf32f(cS[nt][0]);
            pA[1] = tf32f(cS[nt][1]);
            pB[0] = tf32f(cS[nt][2]);
            pB[1] = tf32f(cS[nt][3]);
        }
        __syncthreads();

#pragma unroll
        for (int ks = 0; ks < 8; ks++) {
            const int k = ks * 8;
            uint32_t aP[4];
            const uint32_t* p = PsU + (r0 + lr) * 68 + k + lc;
            aP[0] = p[0]; aP[2] = p[4]; aP[1] = p[8 * 68]; aP[3] = p[8 * 68 + 4];
#pragma unroll
            for (int nt = 0; nt < 8; nt++) {
                uint32_t bV[2];
                bV[0] = VsU[(k + lc) * 72 + nt * 8 + lr];
                bV[1] = VsU[(k + lc + 4) * 72 + nt * 8 + lr];
                mma16n8k8(cO[nt], aP, bV);
            }
        }
    }

    const float invA = 1.0f / lA;
    const float invB = 1.0f / lB;
    float* oA = g_attn + ((size_t)b * Lx + qrA) * Dx + h * DKx;
    float* oB = g_attn + ((size_t)b * Lx + qrB) * Dx + h * DKx;
#pragma unroll
    for (int nt = 0; nt < 8; nt++) {
        const int n = nt * 8 + 2 * lc;
        *(float2*)(oA + n) = make_float2(cO[nt][0] * invA, cO[nt][1] * invA);
        *(float2*)(oB + n) = make_float2(cO[nt][2] * invB, cO[nt][3] * invB);
    }
}

// ---------------- launch ----------------
extern "C" void kernel_launch(void* const* d_in, const int* in_sizes, int n_in,
                              void* d_out, int out_size)
{
    const float* x   = (const float*)d_in[0];
    const float* ts  = (const float*)d_in[1];
    const float* Wq  = (const float*)d_in[4];
    const float* bq  = (const float*)d_in[5];
    const float* Wk  = (const float*)d_in[6];
    const float* bk  = (const float*)d_in[7];
    const float* Wv  = (const float*)d_in[8];
    const float* bv  = (const float*)d_in[9];
    const float* Wo  = (const float*)d_in[10];
    const float* bo  = (const float*)d_in[11];
    const float* lam = (const float*)d_in[12];
    float* out = (float*)d_out;

    float* xh_f; float* xl_f;
    cudaGetSymbolAddress((void**)&xh_f, g_xh);  // resolved at capture; just device ptrs
    cudaGetSymbolAddress((void**)&xl_f, g_xl);

    k_denom<<<1, 1>>>(ts, lam);
    k_bias<<<(Bx*Lx*Lx)/256, 256>>>(ts);

    // pack x and all 4 weight matrices to bf16 hi/lo
    k_pack<<<(4096*512)/256, 256>>>(x, (uint32_t*)xh_f, (uint32_t*)xl_f);
    k_packw<<<dim3((1024*512)/256, 1, 4), 256>>>(Wq, Wk, Wv, Wo);

    cudaFuncSetAttribute(k_gemm_bf16<true>,  cudaFuncAttributeMaxDynamicSharedMemorySize, GEMM2_SMEM);
    cudaFuncSetAttribute(k_gemm_bf16<false>, cudaFuncAttributeMaxDynamicSharedMemorySize, GEMM2_SMEM);
    cudaFuncSetAttribute(k_attn_mma, cudaFuncAttributeMaxDynamicSharedMemorySize, ATTN_SMEM);

    // Q/K/V projections
    k_gemm_bf16<true><<<dim3(Dx/128, (Bx*Lx)/128, 3), 256, GEMM2_SMEM>>>(
        bq, bk, bv, nullptr);

    // flash attention
    k_attn_mma<<<dim3(Lx/64, BHx), 128, ATTN_SMEM>>>();

    // pack attention output, then output projection
    {
        float* gattn_p;
        cudaGetSymbolAddress((void**)&gattn_p, g_attn);
        k_pack<<<(4096*512)/256, 256>>>(gattn_p, (uint32_t*)xh_f, (uint32_t*)xl_f);
    }
    k_gemm_bf16<false><<<dim3(Dx/128, (Bx*Lx)/128, 1), 256, GEMM2_SMEM>>>(
        bo, nullptr, nullptr, out);
}